// round 10
// baseline (speedup 1.0000x reference)
#include <cuda_runtime.h>
#include <cuda_fp16.h>
#include <math.h>

#define HT 128
#define WT 128
#define HS 256
#define WS 256
#define NC 32
#define NV 3
#define ND 48
#define NPIX (HT * WT)

// bit casts (the intrinsics __half2_as_uint / __uint_as_half2 don't exist)
__device__ __forceinline__ unsigned int h2_as_u32(__half2 h) {
    return *reinterpret_cast<unsigned int*>(&h);
}
__device__ __forceinline__ __half2 u32_as_h2(unsigned int u) {
    return *reinterpret_cast<__half2*>(&u);
}

// Static scratch (no allocs allowed)
__device__ __half d_featH[NV * HS * WS * NC];   // (v,y,x,c) channel-last half, ~12.6MB
__device__ float  d_cost[ND * NPIX];            // cost volume (d, pix)
__device__ float  d_proj[NV * 12];

// ---------------------------------------------------------------------------
// Kernel 1: projection matrices via structured inverse:
// tar_proj = [[B, t],[0,0,0,1]]  =>  inv = [[Binv, -Binv t],[0,0,0,1]]
// proj_v = A_v(3x4) @ inv,  A_v = Ks_v @ E_v[:3,:]
// ---------------------------------------------------------------------------
__global__ void setup_kernel(const float* __restrict__ src_exts,
                             const float* __restrict__ src_ints,
                             const float* __restrict__ tar_exts,
                             const float* __restrict__ tar_ints)
{
    if (threadIdx.x != 0) return;
    double B[3][3], tv[3];
    for (int i = 0; i < 3; i++) {
        for (int j = 0; j < 3; j++) {
            double s = 0.0;
            for (int k = 0; k < 3; k++)
                s += (double)tar_ints[i * 3 + k] * (double)tar_exts[k * 4 + j];
            B[i][j] = s;
        }
        double s = 0.0;
        for (int k = 0; k < 3; k++)
            s += (double)tar_ints[i * 3 + k] * (double)tar_exts[k * 4 + 3];
        tv[i] = s;
    }
    double c00 = B[1][1] * B[2][2] - B[1][2] * B[2][1];
    double c01 = B[1][2] * B[2][0] - B[1][0] * B[2][2];
    double c02 = B[1][0] * B[2][1] - B[1][1] * B[2][0];
    double det = B[0][0] * c00 + B[0][1] * c01 + B[0][2] * c02;
    double id = 1.0 / det;
    double Binv[3][3];
    Binv[0][0] = c00 * id;
    Binv[1][0] = c01 * id;
    Binv[2][0] = c02 * id;
    Binv[0][1] = (B[0][2] * B[2][1] - B[0][1] * B[2][2]) * id;
    Binv[1][1] = (B[0][0] * B[2][2] - B[0][2] * B[2][0]) * id;
    Binv[2][1] = (B[0][1] * B[2][0] - B[0][0] * B[2][1]) * id;
    Binv[0][2] = (B[0][1] * B[1][2] - B[0][2] * B[1][1]) * id;
    Binv[1][2] = (B[0][2] * B[1][0] - B[0][0] * B[1][2]) * id;
    Binv[2][2] = (B[0][0] * B[1][1] - B[0][1] * B[1][0]) * id;
    double mt[3];
    for (int i = 0; i < 3; i++)
        mt[i] = -(Binv[i][0] * tv[0] + Binv[i][1] * tv[1] + Binv[i][2] * tv[2]);

    for (int v = 0; v < NV; v++) {
        const float* K = src_ints + v * 9;
        const float* E = src_exts + v * 16;
        double A[3][4];
        for (int i = 0; i < 3; i++)
            for (int j = 0; j < 4; j++) {
                double s = 0.0;
                for (int k = 0; k < 3; k++)
                    s += (double)K[i * 3 + k] * (double)E[k * 4 + j];
                A[i][j] = s;
            }
        for (int i = 0; i < 3; i++) {
            for (int j = 0; j < 3; j++) {
                double s = A[i][0] * Binv[0][j] + A[i][1] * Binv[1][j] + A[i][2] * Binv[2][j];
                d_proj[v * 12 + i * 4 + j] = (float)s;
            }
            double s = A[i][0] * mt[0] + A[i][1] * mt[1] + A[i][2] * mt[2] + A[i][3];
            d_proj[v * 12 + i * 4 + 3] = (float)s;
        }
    }
}

// ---------------------------------------------------------------------------
// Kernel 2: transpose+convert (V,C,H,W) fp32 -> (V,H,W,C) half (64B/pixel)
// ---------------------------------------------------------------------------
__global__ void transpose_kernel(const float* __restrict__ src)
{
    int idx = blockIdx.x * blockDim.x + threadIdx.x;
    if (idx >= NV * HS * WS) return;
    int v = idx >> 16;
    int y = (idx >> 8) & (HS - 1);
    int x = idx & (WS - 1);
    const float* in = src + ((size_t)(v * NC) * HS + y) * WS + x;
    __half2 buf[NC / 2];
#pragma unroll
    for (int c = 0; c < NC / 2; c++) {
        float a = in[(size_t)(2 * c) * HS * WS];
        float b = in[(size_t)(2 * c + 1) * HS * WS];
        buf[c] = __floats2half2_rn(a, b);
    }
    uint4* out = reinterpret_cast<uint4*>((char*)d_featH + (size_t)idx * (NC * 2));
    const uint4* bp = reinterpret_cast<const uint4*>(buf);
#pragma unroll
    for (int q = 0; q < 4; q++) out[q] = bp[q];
}

// ---------------------------------------------------------------------------
// Kernel 3: cost volume, half features. Block = 64 px x 8 depths, 8 warps;
// warp = 8 pixels x 4 channel-groups (uint4 = 8 half channels per lane).
// Staging computes weights (as half2 broadcasts) + packed offsets into SMEM.
// ---------------------------------------------------------------------------
__global__ void __launch_bounds__(256, 4)
cost_kernel(const float* __restrict__ nearfar)
{
    __shared__ uint4 s_wgt[8][NV][64];   // (w00,w01,w10,w11) as half2 broadcasts
    __shared__ int   s_word[8][NV][64];  // a00 byteoff | xstep<<24 | ystep<<25

    const int tid  = threadIdx.x;
    const int pix0 = blockIdx.x * 64;
    const int d0   = blockIdx.y * 8;

    // ---- staging: 8*3*64 = 1536 coord tasks, 6 per thread ----
#pragma unroll
    for (int e = tid; e < 8 * NV * 64; e += 256) {
        const int p  = e & 63;
        const int v  = (e >> 6) % NV;
        const int dd = e / (NV * 64);
        const int pix = pix0 + p;
        const int d   = d0 + dd;

        const float nearv = nearfar[pix];
        const float farv  = nearfar[NPIX + pix];
        const float depth = fmaf((farv - nearv) * (1.0f / (ND - 1)), (float)d, nearv);
        const int x = pix & (WT - 1);
        const int y = pix >> 7;
        const float X = (float)x + 0.5f;
        const float Y = (float)y + 0.5f;

        const float* P = d_proj + v * 12;
        float px_ = fmaf(fmaf(P[0], X, fmaf(P[1], Y, P[2])), depth, P[3]);
        float py_ = fmaf(fmaf(P[4], X, fmaf(P[5], Y, P[6])), depth, P[7]);
        float pz_ = fmaf(fmaf(P[8], X, fmaf(P[9], Y, P[10])), depth, P[11]);
        pz_ = fmaxf(pz_, 1e-6f);
        float gx = px_ / pz_ - 0.5f;
        float gy = py_ / pz_ - 0.5f;
        gx = fminf(fmaxf(gx, -1.0e6f), 1.0e6f);
        gy = fminf(fmaxf(gy, -1.0e6f), 1.0e6f);
        float x0f = floorf(gx), y0f = floorf(gy);
        float wx = gx - x0f, wy = gy - y0f;
        int x0 = (int)x0f, y0 = (int)y0f;
        int x1 = x0 + 1, y1 = y0 + 1;
        float w00 = (1.f - wy) * (1.f - wx);
        float w01 = (1.f - wy) * wx;
        float w10 = wy * (1.f - wx);
        float w11 = wy * wx;
        bool vx0 = ((unsigned)x0 < WS);
        bool vx1 = ((unsigned)x1 < WS);
        bool vy0 = ((unsigned)y0 < HS);
        bool vy1 = ((unsigned)y1 < HS);
        if (!(vy0 & vx0)) w00 = 0.f;
        if (!(vy0 & vx1)) w01 = 0.f;
        if (!(vy1 & vx0)) w10 = 0.f;
        if (!(vy1 & vx1)) w11 = 0.f;
        int cx0 = min(max(x0, 0), WS - 1);
        int cy0 = min(max(y0, 0), HS - 1);
        int cx1 = min(max(x1, 0), WS - 1);
        int cy1 = min(max(y1, 0), HS - 1);

        int a00 = (cy0 * WS + cx0) * (NC * 2);     // half: 64B per pixel
        uint4 wh;
        wh.x = h2_as_u32(__float2half2_rn(w00));
        wh.y = h2_as_u32(__float2half2_rn(w01));
        wh.z = h2_as_u32(__float2half2_rn(w10));
        wh.w = h2_as_u32(__float2half2_rn(w11));
        s_wgt[dd][v][p]  = wh;
        s_word[dd][v][p] = a00 | ((cx1 - cx0) << 24) | ((cy1 - cy0) << 25);
    }
    __syncthreads();

    // ---- main loop ----
    const int lane = tid & 31;
    const int w    = tid >> 5;
    const int cg   = lane & 3;            // 4 channel groups x 8 half channels
    const int pxl  = lane >> 2;           // 8 pixels per warp
    const int pl   = w * 8 + pxl;
    const int pix  = pix0 + pl;

    const char* fbase = (const char*)d_featH + cg * 16;

#pragma unroll
    for (int dd = 0; dd < 8; dd++) {
        float s1[8] = {0.f, 0.f, 0.f, 0.f, 0.f, 0.f, 0.f, 0.f};
        float S2 = 0.f;
#pragma unroll
        for (int v = 0; v < NV; v++) {
            const uint4 wh  = s_wgt[dd][v][pl];
            const int  word = s_word[dd][v][pl];
            const char* base = fbase + (size_t)v * (HS * WS * NC * 2) + (word & 0xFFFFFF);
            const int dx = (word >> 18) & 64;       // bit24 -> 64 B
            const int dy = (word >> 11) & 16384;    // bit25 -> 16384 B (row)

            const uint4 t00 = *reinterpret_cast<const uint4*>(base);
            const uint4 t01 = *reinterpret_cast<const uint4*>(base + dx);
            const uint4 t10 = *reinterpret_cast<const uint4*>(base + dy);
            const uint4 t11 = *reinterpret_cast<const uint4*>(base + dy + dx);

            const __half2 h00 = u32_as_h2(wh.x);
            const __half2 h01 = u32_as_h2(wh.y);
            const __half2 h10 = u32_as_h2(wh.z);
            const __half2 h11 = u32_as_h2(wh.w);

#pragma unroll
            for (int j = 0; j < 4; j++) {
                __half2 a = __hmul2(h00, u32_as_h2((&t00.x)[j]));
                a = __hfma2(h01, u32_as_h2((&t01.x)[j]), a);
                a = __hfma2(h10, u32_as_h2((&t10.x)[j]), a);
                a = __hfma2(h11, u32_as_h2((&t11.x)[j]), a);
                float2 f = __half22float2(a);
                s1[2 * j]     += f.x;
                s1[2 * j + 1] += f.y;
                S2 = fmaf(f.x, f.x, S2);
                S2 = fmaf(f.y, f.y, S2);
            }
        }

        float q = 0.f;
#pragma unroll
        for (int j = 0; j < 8; j++) q = fmaf(s1[j], s1[j], q);

#pragma unroll
        for (int off = 1; off < 4; off <<= 1) {
            q  += __shfl_xor_sync(0xffffffffu, q, off);
            S2 += __shfl_xor_sync(0xffffffffu, S2, off);
        }
        if (cg == 0)
            d_cost[(d0 + dd) * NPIX + pix] =
                S2 * (1.0f / (NV * NC)) - q * (1.0f / (NV * NV * NC));
    }
}

// ---------------------------------------------------------------------------
// Kernel 4: softmax over depth -> expected depth, CI
// ---------------------------------------------------------------------------
__global__ void depth_kernel(const float* __restrict__ nearfar, float* __restrict__ out)
{
    int pix = blockIdx.x * blockDim.x + threadIdx.x;
    if (pix >= NPIX) return;
    const float nearv = nearfar[pix];
    const float farv  = nearfar[NPIX + pix];
    const float step  = (farv - nearv) * (1.0f / (ND - 1));

    float c[ND];
    float m = -1e30f;
#pragma unroll
    for (int d = 0; d < ND; d++) {
        c[d] = -d_cost[d * NPIX + pix];
        m = fmaxf(m, c[d]);
    }
    float Z = 0.f, S1 = 0.f;
#pragma unroll
    for (int d = 0; d < ND; d++) {
        float e = expf(c[d] - m);
        c[d] = e;
        Z += e;
        S1 = fmaf(e, fmaf(step, (float)d, nearv), S1);
    }
    const float invZ = 1.0f / Z;
    const float depth = S1 * invZ;
    float Svar = 0.f;
#pragma unroll
    for (int d = 0; d < ND; d++) {
        float dv = fmaf(step, (float)d, nearv);
        float diff = dv - depth;
        Svar = fmaf(c[d], diff * diff, Svar);
    }
    float var = Svar * invZ;
    float hc = sqrtf(fmaxf(var, 1e-12f));
    out[pix] = depth;
    out[NPIX + pix] = fmaxf(depth - hc, nearv);
    out[2 * NPIX + pix] = fminf(depth + hc, farv);
}

// ---------------------------------------------------------------------------
extern "C" void kernel_launch(void* const* d_in, const int* in_sizes, int n_in,
                              void* d_out, int out_size)
{
    const float* src_feat = (const float*)d_in[0];
    const float* src_exts = (const float*)d_in[1];
    const float* src_ints = (const float*)d_in[2];
    const float* tar_exts = (const float*)d_in[3];
    const float* tar_ints = (const float*)d_in[4];
    const float* near_far = (const float*)d_in[5];
    (void)in_sizes; (void)n_in; (void)out_size;

    setup_kernel<<<1, 32>>>(src_exts, src_ints, tar_exts, tar_ints);

    transpose_kernel<<<(NV * HS * WS + 255) / 256, 256>>>(src_feat);

    dim3 cg(NPIX / 64, ND / 8);
    cost_kernel<<<cg, 256>>>(near_far);

    depth_kernel<<<(NPIX + 127) / 128, 128>>>(near_far, (float*)d_out);
}

// round 13
// speedup vs baseline: 1.1905x; 1.1905x over previous
#include <cuda_runtime.h>
#include <math.h>

#define HT 128
#define WT 128
#define HS 256
#define WS 256
#define NC 32
#define NV 3
#define ND 48
#define NPIX (HT * WT)

// Static scratch (no allocs allowed)
__device__ float d_featT[NV * HS * WS * NC];   // (v,y,x,c) channel-last, ~25MB
__device__ float d_costT[NPIX * ND];           // cost volume (pix, d) -- transposed
__device__ float d_proj[NV * 12];

// ---------------------------------------------------------------------------
// Kernel 1: projection matrices via structured inverse:
// tar_proj = [[B, t],[0,0,0,1]] => inv = [[Binv, -Binv t],[0,0,0,1]]
// proj_v = (Ks_v E_v[:3,:]) @ inv
// ---------------------------------------------------------------------------
__global__ void setup_kernel(const float* __restrict__ src_exts,
                             const float* __restrict__ src_ints,
                             const float* __restrict__ tar_exts,
                             const float* __restrict__ tar_ints)
{
    if (threadIdx.x != 0) return;
    double B[3][3], tv[3];
    for (int i = 0; i < 3; i++) {
        for (int j = 0; j < 3; j++) {
            double s = 0.0;
            for (int k = 0; k < 3; k++)
                s += (double)tar_ints[i * 3 + k] * (double)tar_exts[k * 4 + j];
            B[i][j] = s;
        }
        double s = 0.0;
        for (int k = 0; k < 3; k++)
            s += (double)tar_ints[i * 3 + k] * (double)tar_exts[k * 4 + 3];
        tv[i] = s;
    }
    double c00 = B[1][1] * B[2][2] - B[1][2] * B[2][1];
    double c01 = B[1][2] * B[2][0] - B[1][0] * B[2][2];
    double c02 = B[1][0] * B[2][1] - B[1][1] * B[2][0];
    double det = B[0][0] * c00 + B[0][1] * c01 + B[0][2] * c02;
    double id = 1.0 / det;
    double Binv[3][3];
    Binv[0][0] = c00 * id;
    Binv[1][0] = c01 * id;
    Binv[2][0] = c02 * id;
    Binv[0][1] = (B[0][2] * B[2][1] - B[0][1] * B[2][2]) * id;
    Binv[1][1] = (B[0][0] * B[2][2] - B[0][2] * B[2][0]) * id;
    Binv[2][1] = (B[0][1] * B[2][0] - B[0][0] * B[2][1]) * id;
    Binv[0][2] = (B[0][1] * B[1][2] - B[0][2] * B[1][1]) * id;
    Binv[1][2] = (B[0][2] * B[1][0] - B[0][0] * B[1][2]) * id;
    Binv[2][2] = (B[0][0] * B[1][1] - B[0][1] * B[1][0]) * id;
    double mt[3];
    for (int i = 0; i < 3; i++)
        mt[i] = -(Binv[i][0] * tv[0] + Binv[i][1] * tv[1] + Binv[i][2] * tv[2]);

    for (int v = 0; v < NV; v++) {
        const float* K = src_ints + v * 9;
        const float* E = src_exts + v * 16;
        double A[3][4];
        for (int i = 0; i < 3; i++)
            for (int j = 0; j < 4; j++) {
                double s = 0.0;
                for (int k = 0; k < 3; k++)
                    s += (double)K[i * 3 + k] * (double)E[k * 4 + j];
                A[i][j] = s;
            }
        for (int i = 0; i < 3; i++) {
            for (int j = 0; j < 3; j++) {
                double s = A[i][0] * Binv[0][j] + A[i][1] * Binv[1][j] + A[i][2] * Binv[2][j];
                d_proj[v * 12 + i * 4 + j] = (float)s;
            }
            double s = A[i][0] * mt[0] + A[i][1] * mt[1] + A[i][2] * mt[2] + A[i][3];
            d_proj[v * 12 + i * 4 + 3] = (float)s;
        }
    }
}

// ---------------------------------------------------------------------------
// Kernel 2: transpose (V,C,H,W) -> (V,H,W,C): one tap = one 128B line
// ---------------------------------------------------------------------------
__global__ void transpose_kernel(const float* __restrict__ src)
{
    int idx = blockIdx.x * blockDim.x + threadIdx.x;
    if (idx >= NV * HS * WS) return;
    int v = idx >> 16;
    int y = (idx >> 8) & (HS - 1);
    int x = idx & (WS - 1);
    const float* in = src + ((size_t)(v * NC) * HS + y) * WS + x;
    float buf[NC];
#pragma unroll
    for (int c = 0; c < NC; c++) buf[c] = in[(size_t)c * HS * WS];
    float4* out = reinterpret_cast<float4*>(d_featT + (size_t)idx * NC);
#pragma unroll
    for (int c4 = 0; c4 < NC / 4; c4++)
        out[c4] = make_float4(buf[c4 * 4], buf[c4 * 4 + 1], buf[c4 * 4 + 2], buf[c4 * 4 + 3]);
}

// ---------------------------------------------------------------------------
// Kernel 3: cost volume. Block = 32 px x 8 depths. Staging computes coords
// inline -> SMEM stores float4 weights + int4 ABSOLUTE tap byte-offsets
// (no unpack ALU in main loop). Single-value reduction (V*S2 - q).
// Results staged in SMEM, written transposed (pix, d) coalesced.
// ---------------------------------------------------------------------------
__global__ void __launch_bounds__(256, 4)
cost_kernel(const float* __restrict__ nearfar)
{
    __shared__ float4 s_wgt[8][NV][32];
    __shared__ int4   s_off[8][NV][32];
    __shared__ float  s_res[32][8];

    const int tid  = threadIdx.x;
    const int pix0 = blockIdx.x * 32;
    const int d0   = blockIdx.y * 8;

    // ---- staging: 768 coord tasks, 3 per thread ----
#pragma unroll
    for (int e = tid; e < 8 * NV * 32; e += 256) {
        const int p  = e & 31;
        const int v  = (e >> 5) % NV;
        const int dd = e / (NV * 32);
        const int pix = pix0 + p;
        const int d   = d0 + dd;

        const float nearv = nearfar[pix];
        const float farv  = nearfar[NPIX + pix];
        const float depth = fmaf((farv - nearv) * (1.0f / (ND - 1)), (float)d, nearv);
        const int x = pix & (WT - 1);
        const int y = pix >> 7;
        const float X = (float)x + 0.5f;
        const float Y = (float)y + 0.5f;

        const float* P = d_proj + v * 12;
        float px_ = fmaf(fmaf(P[0], X, fmaf(P[1], Y, P[2])), depth, P[3]);
        float py_ = fmaf(fmaf(P[4], X, fmaf(P[5], Y, P[6])), depth, P[7]);
        float pz_ = fmaf(fmaf(P[8], X, fmaf(P[9], Y, P[10])), depth, P[11]);
        pz_ = fmaxf(pz_, 1e-6f);
        float gx = px_ / pz_ - 0.5f;
        float gy = py_ / pz_ - 0.5f;
        gx = fminf(fmaxf(gx, -1.0e6f), 1.0e6f);
        gy = fminf(fmaxf(gy, -1.0e6f), 1.0e6f);
        float x0f = floorf(gx), y0f = floorf(gy);
        float wx = gx - x0f, wy = gy - y0f;
        int x0 = (int)x0f, y0 = (int)y0f;
        int x1 = x0 + 1, y1 = y0 + 1;
        float w00 = (1.f - wy) * (1.f - wx);
        float w01 = (1.f - wy) * wx;
        float w10 = wy * (1.f - wx);
        float w11 = wy * wx;
        bool vx0 = ((unsigned)x0 < WS);
        bool vx1 = ((unsigned)x1 < WS);
        bool vy0 = ((unsigned)y0 < HS);
        bool vy1 = ((unsigned)y1 < HS);
        if (!(vy0 & vx0)) w00 = 0.f;
        if (!(vy0 & vx1)) w01 = 0.f;
        if (!(vy1 & vx0)) w10 = 0.f;
        if (!(vy1 & vx1)) w11 = 0.f;
        int cx0 = min(max(x0, 0), WS - 1);
        int cy0 = min(max(y0, 0), HS - 1);
        int cx1 = min(max(x1, 0), WS - 1);
        int cy1 = min(max(y1, 0), HS - 1);

        const int vb = v * (HS * WS * NC * 4);
        const int r0 = cy0 * (WS * NC * 4);
        const int r1 = cy1 * (WS * NC * 4);
        int4 O;
        O.x = vb + r0 + cx0 * (NC * 4);
        O.y = vb + r0 + cx1 * (NC * 4);
        O.z = vb + r1 + cx0 * (NC * 4);
        O.w = vb + r1 + cx1 * (NC * 4);

        s_wgt[dd][v][p] = make_float4(w00, w01, w10, w11);
        s_off[dd][v][p] = O;
    }
    __syncthreads();

    // ---- main loop: warp = 4 px x 8 channel groups ----
    const int lane = tid & 31;
    const int w    = tid >> 5;
    const int cg   = lane & 7;
    const int pxl  = lane >> 3;
    const int pl   = w * 4 + pxl;

    const char* fbase = (const char*)d_featT + cg * 16;

#pragma unroll
    for (int dd = 0; dd < 8; dd++) {
        float4 s1 = make_float4(0.f, 0.f, 0.f, 0.f);
        float S2 = 0.f;
#pragma unroll
        for (int v = 0; v < NV; v++) {
            const float4 W = s_wgt[dd][v][pl];
            const int4   O = s_off[dd][v][pl];

            const float4 t00 = *reinterpret_cast<const float4*>(fbase + O.x);
            const float4 t01 = *reinterpret_cast<const float4*>(fbase + O.y);
            const float4 t10 = *reinterpret_cast<const float4*>(fbase + O.z);
            const float4 t11 = *reinterpret_cast<const float4*>(fbase + O.w);

            float4 wv;
            wv.x = fmaf(W.x, t00.x, fmaf(W.y, t01.x, fmaf(W.z, t10.x, W.w * t11.x)));
            wv.y = fmaf(W.x, t00.y, fmaf(W.y, t01.y, fmaf(W.z, t10.y, W.w * t11.y)));
            wv.z = fmaf(W.x, t00.z, fmaf(W.y, t01.z, fmaf(W.z, t10.z, W.w * t11.z)));
            wv.w = fmaf(W.x, t00.w, fmaf(W.y, t01.w, fmaf(W.z, t10.w, W.w * t11.w)));

            s1.x += wv.x; s1.y += wv.y; s1.z += wv.z; s1.w += wv.w;
            S2 = fmaf(wv.x, wv.x, S2);
            S2 = fmaf(wv.y, wv.y, S2);
            S2 = fmaf(wv.z, wv.z, S2);
            S2 = fmaf(wv.w, wv.w, S2);
        }

        float q = fmaf(s1.x, s1.x, fmaf(s1.y, s1.y, fmaf(s1.z, s1.z, s1.w * s1.w)));
        float r = fmaf((float)NV, S2, -q);      // V*S2 - q : single reduce value
#pragma unroll
        for (int off = 1; off < 8; off <<= 1)
            r += __shfl_xor_sync(0xffffffffu, r, off);
        if (cg == 0)
            s_res[pl][dd] = r * (1.0f / (NV * NV * NC));
    }
    __syncthreads();

    // ---- coalesced transposed write: (pix, d) ----
    {
        const int pl2 = tid >> 3;      // 0..31
        const int dd2 = tid & 7;       // 0..7
        d_costT[(pix0 + pl2) * ND + d0 + dd2] = s_res[pl2][dd2];
    }
}

// ---------------------------------------------------------------------------
// Kernel 4: warp-per-pixel softmax over depth -> expected depth, CI
// ---------------------------------------------------------------------------
__global__ void __launch_bounds__(256)
depth_kernel(const float* __restrict__ nearfar, float* __restrict__ out)
{
    const int lane = threadIdx.x & 31;
    const int wid  = threadIdx.x >> 5;
    const int pix  = blockIdx.x * 8 + wid;

    const float nearv = nearfar[pix];
    const float farv  = nearfar[NPIX + pix];
    const float step  = (farv - nearv) * (1.0f / (ND - 1));
    const float* cp = d_costT + pix * ND;

    // lane covers depth = lane, and (lane<16) depth = 32+lane
    const float n0 = -cp[lane];
    const float n1 = (lane < 16) ? -cp[32 + lane] : -1e30f;

    float m = fmaxf(n0, n1);
#pragma unroll
    for (int off = 16; off > 0; off >>= 1)
        m = fmaxf(m, __shfl_xor_sync(0xffffffffu, m, off));

    const float dv0 = fmaf(step, (float)lane, nearv);
    const float dv1 = fmaf(step, (float)(32 + lane), nearv);
    const float e0 = __expf(n0 - m);
    const float e1 = (lane < 16) ? __expf(n1 - m) : 0.f;

    float Z  = e0 + e1;
    float S1 = fmaf(e0, dv0, e1 * dv1);
#pragma unroll
    for (int off = 16; off > 0; off >>= 1) {
        Z  += __shfl_xor_sync(0xffffffffu, Z, off);
        S1 += __shfl_xor_sync(0xffffffffu, S1, off);
    }
    const float invZ = 1.0f / Z;
    const float depth = S1 * invZ;

    float d0f = dv0 - depth;
    float d1f = dv1 - depth;
    float Svar = fmaf(e0, d0f * d0f, e1 * (d1f * d1f));
#pragma unroll
    for (int off = 16; off > 0; off >>= 1)
        Svar += __shfl_xor_sync(0xffffffffu, Svar, off);

    if (lane == 0) {
        const float var = Svar * invZ;
        const float hc = sqrtf(fmaxf(var, 1e-12f));
        out[pix] = depth;
        out[NPIX + pix] = fmaxf(depth - hc, nearv);
        out[2 * NPIX + pix] = fminf(depth + hc, farv);
    }
}

// ---------------------------------------------------------------------------
extern "C" void kernel_launch(void* const* d_in, const int* in_sizes, int n_in,
                              void* d_out, int out_size)
{
    const float* src_feat = (const float*)d_in[0];
    const float* src_exts = (const float*)d_in[1];
    const float* src_ints = (const float*)d_in[2];
    const float* tar_exts = (const float*)d_in[3];
    const float* tar_ints = (const float*)d_in[4];
    const float* near_far = (const float*)d_in[5];
    (void)in_sizes; (void)n_in; (void)out_size;

    setup_kernel<<<1, 32>>>(src_exts, src_ints, tar_exts, tar_ints);

    transpose_kernel<<<(NV * HS * WS + 255) / 256, 256>>>(src_feat);

    dim3 cg(NPIX / 32, ND / 8);
    cost_kernel<<<cg, 256>>>(near_far);

    depth_kernel<<<NPIX / 8, 256>>>(near_far, (float*)d_out);
}

// round 14
// speedup vs baseline: 1.4057x; 1.1808x over previous
#include <cuda_runtime.h>
#include <cuda_fp16.h>
#include <math.h>

#define HT 128
#define WT 128
#define HS 256
#define WS 256
#define NC 32
#define NV 3
#define ND 48
#define NPIX (HT * WT)
#define XP 128                      // x-pair count per row
#define PAIR_BYTES 128              // one pair-line: 32 ch x (L,R) half

__device__ __forceinline__ __half2 u32_as_h2(unsigned int u) {
    return *reinterpret_cast<__half2*>(&u);
}

// Static scratch (no allocs allowed)
// pair layout: [parity][v][y][xp] -> 128B line: half2(L_c, R_c) for c=0..31
// L = src(x = 2*xp + parity), R = src(min(x+1, 255))
__device__ __half d_pairH[2 * NV * HS * XP * 2 * NC];   // 25.2MB
__device__ float  d_costT[NPIX * ND];                   // cost volume (pix, d)
__device__ float  d_proj[NV * 12];

// ---------------------------------------------------------------------------
// Kernel 1: projection matrices via structured inverse
// ---------------------------------------------------------------------------
__global__ void setup_kernel(const float* __restrict__ src_exts,
                             const float* __restrict__ src_ints,
                             const float* __restrict__ tar_exts,
                             const float* __restrict__ tar_ints)
{
    if (threadIdx.x != 0) return;
    double B[3][3], tv[3];
    for (int i = 0; i < 3; i++) {
        for (int j = 0; j < 3; j++) {
            double s = 0.0;
            for (int k = 0; k < 3; k++)
                s += (double)tar_ints[i * 3 + k] * (double)tar_exts[k * 4 + j];
            B[i][j] = s;
        }
        double s = 0.0;
        for (int k = 0; k < 3; k++)
            s += (double)tar_ints[i * 3 + k] * (double)tar_exts[k * 4 + 3];
        tv[i] = s;
    }
    double c00 = B[1][1] * B[2][2] - B[1][2] * B[2][1];
    double c01 = B[1][2] * B[2][0] - B[1][0] * B[2][2];
    double c02 = B[1][0] * B[2][1] - B[1][1] * B[2][0];
    double det = B[0][0] * c00 + B[0][1] * c01 + B[0][2] * c02;
    double id = 1.0 / det;
    double Binv[3][3];
    Binv[0][0] = c00 * id;
    Binv[1][0] = c01 * id;
    Binv[2][0] = c02 * id;
    Binv[0][1] = (B[0][2] * B[2][1] - B[0][1] * B[2][2]) * id;
    Binv[1][1] = (B[0][0] * B[2][2] - B[0][2] * B[2][0]) * id;
    Binv[2][1] = (B[0][1] * B[2][0] - B[0][0] * B[2][1]) * id;
    Binv[0][2] = (B[0][1] * B[1][2] - B[0][2] * B[1][1]) * id;
    Binv[1][2] = (B[0][2] * B[1][0] - B[0][0] * B[1][2]) * id;
    Binv[2][2] = (B[0][0] * B[1][1] - B[0][1] * B[1][0]) * id;
    double mt[3];
    for (int i = 0; i < 3; i++)
        mt[i] = -(Binv[i][0] * tv[0] + Binv[i][1] * tv[1] + Binv[i][2] * tv[2]);

    for (int v = 0; v < NV; v++) {
        const float* K = src_ints + v * 9;
        const float* E = src_exts + v * 16;
        double A[3][4];
        for (int i = 0; i < 3; i++)
            for (int j = 0; j < 4; j++) {
                double s = 0.0;
                for (int k = 0; k < 3; k++)
                    s += (double)K[i * 3 + k] * (double)E[k * 4 + j];
                A[i][j] = s;
            }
        for (int i = 0; i < 3; i++) {
            for (int j = 0; j < 3; j++) {
                double s = A[i][0] * Binv[0][j] + A[i][1] * Binv[1][j] + A[i][2] * Binv[2][j];
                d_proj[v * 12 + i * 4 + j] = (float)s;
            }
            double s = A[i][0] * mt[0] + A[i][1] * mt[1] + A[i][2] * mt[2] + A[i][3];
            d_proj[v * 12 + i * 4 + 3] = (float)s;
        }
    }
}

// ---------------------------------------------------------------------------
// Kernel 2: build fp16 interleaved pair lines from (V,C,H,W) fp32 src.
// Thread per (parity, v, y, xp): loads 32 ch of L and R, writes one 128B line.
// ---------------------------------------------------------------------------
__global__ void pair_build_kernel(const float* __restrict__ src)
{
    int idx = blockIdx.x * blockDim.x + threadIdx.x;     // 2*NV*HS*XP = 196608
    if (idx >= 2 * NV * HS * XP) return;
    int xp = idx & (XP - 1);
    int y  = (idx >> 7) & (HS - 1);
    int pv = idx >> 15;            // parity*NV + v
    int v  = pv % NV;
    int parity = pv / NV;
    int xL = 2 * xp + parity;
    int dR = (xL + 1 < WS) ? 1 : 0;

    const float* base = src + ((size_t)(v * NC) * HS + y) * WS + xL;
    __half2 buf[NC];
#pragma unroll
    for (int c = 0; c < NC; c++) {
        float L = base[(size_t)c * HS * WS];
        float R = base[(size_t)c * HS * WS + dR];
        buf[c] = __floats2half2_rn(L, R);
    }
    uint4* out = reinterpret_cast<uint4*>((char*)d_pairH + (size_t)idx * PAIR_BYTES);
    const uint4* bp = reinterpret_cast<const uint4*>(buf);
#pragma unroll
    for (int q = 0; q < 8; q++) out[q] = bp[q];
}

// ---------------------------------------------------------------------------
// Kernel 3: cost volume. Block = 32 px x 8 depths. Staging computes coords
// inline: folded weights + 2 absolute pair-line offsets (y0, y1) per view.
// Main loop: 2 LDG.128 per px-view (x-pair in one line) -> 24 wf/warp-depth.
// ---------------------------------------------------------------------------
__global__ void __launch_bounds__(256, 4)
cost_kernel(const float* __restrict__ nearfar)
{
    __shared__ float4 s_wgt[8][NV][32];   // folded (w00,w01,w10,w11)
    __shared__ int2   s_off[8][NV][32];   // byte offsets of y0 / y1 pair-lines
    __shared__ float  s_res[32][8];

    const int tid  = threadIdx.x;
    const int pix0 = blockIdx.x * 32;
    const int d0   = blockIdx.y * 8;

    // ---- staging: 768 coord tasks, 3 per thread ----
#pragma unroll
    for (int e = tid; e < 8 * NV * 32; e += 256) {
        const int p  = e & 31;
        const int v  = (e >> 5) % NV;
        const int dd = e / (NV * 32);
        const int pix = pix0 + p;
        const int d   = d0 + dd;

        const float nearv = nearfar[pix];
        const float farv  = nearfar[NPIX + pix];
        const float depth = fmaf((farv - nearv) * (1.0f / (ND - 1)), (float)d, nearv);
        const int x = pix & (WT - 1);
        const int y = pix >> 7;
        const float X = (float)x + 0.5f;
        const float Y = (float)y + 0.5f;

        const float* P = d_proj + v * 12;
        float px_ = fmaf(fmaf(P[0], X, fmaf(P[1], Y, P[2])), depth, P[3]);
        float py_ = fmaf(fmaf(P[4], X, fmaf(P[5], Y, P[6])), depth, P[7]);
        float pz_ = fmaf(fmaf(P[8], X, fmaf(P[9], Y, P[10])), depth, P[11]);
        pz_ = fmaxf(pz_, 1e-6f);
        float gx = px_ / pz_ - 0.5f;
        float gy = py_ / pz_ - 0.5f;
        gx = fminf(fmaxf(gx, -1.0e6f), 1.0e6f);
        gy = fminf(fmaxf(gy, -1.0e6f), 1.0e6f);
        float x0f = floorf(gx), y0f = floorf(gy);
        float wx = gx - x0f, wy = gy - y0f;
        int x0 = (int)x0f, y0 = (int)y0f;
        int x1 = x0 + 1, y1 = y0 + 1;
        float w00 = (1.f - wy) * (1.f - wx);
        float w01 = (1.f - wy) * wx;
        float w10 = wy * (1.f - wx);
        float w11 = wy * wx;
        bool vx0 = ((unsigned)x0 < WS);
        bool vx1 = ((unsigned)x1 < WS);
        bool vy0 = ((unsigned)y0 < HS);
        bool vy1 = ((unsigned)y1 < HS);
        if (!(vy0 & vx0)) w00 = 0.f;
        if (!(vy0 & vx1)) w01 = 0.f;
        if (!(vy1 & vx0)) w10 = 0.f;
        if (!(vy1 & vx1)) w11 = 0.f;
        int cx0 = min(max(x0, 0), WS - 1);
        int cy0 = min(max(y0, 0), HS - 1);
        int cx1 = min(max(x1, 0), WS - 1);
        int cy1 = min(max(y1, 0), HS - 1);

        // x-fold: when both x taps clamp to the same column, give the pair's
        // left element the combined weight; right element weight 0.
        if (cx1 == cx0) {
            w00 += w01; w01 = 0.f;
            w10 += w11; w11 = 0.f;
        }
        const int parity = cx0 & 1;
        const int xp = cx0 >> 1;
        const int pvb = (parity * NV + v) * HS;
        int2 O;
        O.x = ((pvb + cy0) * XP + xp) * PAIR_BYTES;
        O.y = ((pvb + cy1) * XP + xp) * PAIR_BYTES;

        s_wgt[dd][v][p] = make_float4(w00, w01, w10, w11);
        s_off[dd][v][p] = O;
    }
    __syncthreads();

    // ---- main loop: warp = 4 px x 8 channel groups (4 ch pairs each) ----
    const int lane = tid & 31;
    const int w    = tid >> 5;
    const int cg   = lane & 7;
    const int pxl  = lane >> 3;
    const int pl   = w * 4 + pxl;

    const char* fbase = (const char*)d_pairH + cg * 16;

#pragma unroll
    for (int dd = 0; dd < 8; dd++) {
        float s1[4] = {0.f, 0.f, 0.f, 0.f};
        float S2 = 0.f;
#pragma unroll
        for (int v = 0; v < NV; v++) {
            const float4 W = s_wgt[dd][v][pl];
            const int2   O = s_off[dd][v][pl];

            const uint4 r0 = *reinterpret_cast<const uint4*>(fbase + O.x);
            const uint4 r1 = *reinterpret_cast<const uint4*>(fbase + O.y);

#pragma unroll
            for (int j = 0; j < 4; j++) {
                const float2 a0 = __half22float2(u32_as_h2((&r0.x)[j]));  // (L,R) y0
                const float2 a1 = __half22float2(u32_as_h2((&r1.x)[j]));  // (L,R) y1
                const float wv = fmaf(W.x, a0.x, fmaf(W.y, a0.y,
                                 fmaf(W.z, a1.x, W.w * a1.y)));
                s1[j] += wv;
                S2 = fmaf(wv, wv, S2);
            }
        }

        float q = fmaf(s1[0], s1[0], fmaf(s1[1], s1[1],
                  fmaf(s1[2], s1[2], s1[3] * s1[3])));
        float r = fmaf((float)NV, S2, -q);
#pragma unroll
        for (int off = 1; off < 8; off <<= 1)
            r += __shfl_xor_sync(0xffffffffu, r, off);
        if (cg == 0)
            s_res[pl][dd] = r * (1.0f / (NV * NV * NC));
    }
    __syncthreads();

    // ---- coalesced transposed write: (pix, d) ----
    {
        const int pl2 = tid >> 3;
        const int dd2 = tid & 7;
        d_costT[(pix0 + pl2) * ND + d0 + dd2] = s_res[pl2][dd2];
    }
}

// ---------------------------------------------------------------------------
// Kernel 4: warp-per-pixel softmax over depth -> expected depth, CI
// ---------------------------------------------------------------------------
__global__ void __launch_bounds__(256)
depth_kernel(const float* __restrict__ nearfar, float* __restrict__ out)
{
    const int lane = threadIdx.x & 31;
    const int wid  = threadIdx.x >> 5;
    const int pix  = blockIdx.x * 8 + wid;

    const float nearv = nearfar[pix];
    const float farv  = nearfar[NPIX + pix];
    const float step  = (farv - nearv) * (1.0f / (ND - 1));
    const float* cp = d_costT + pix * ND;

    const float n0 = -cp[lane];
    const float n1 = (lane < 16) ? -cp[32 + lane] : -1e30f;

    float m = fmaxf(n0, n1);
#pragma unroll
    for (int off = 16; off > 0; off >>= 1)
        m = fmaxf(m, __shfl_xor_sync(0xffffffffu, m, off));

    const float dv0 = fmaf(step, (float)lane, nearv);
    const float dv1 = fmaf(step, (float)(32 + lane), nearv);
    const float e0 = __expf(n0 - m);
    const float e1 = (lane < 16) ? __expf(n1 - m) : 0.f;

    float Z  = e0 + e1;
    float S1 = fmaf(e0, dv0, e1 * dv1);
#pragma unroll
    for (int off = 16; off > 0; off >>= 1) {
        Z  += __shfl_xor_sync(0xffffffffu, Z, off);
        S1 += __shfl_xor_sync(0xffffffffu, S1, off);
    }
    const float invZ = 1.0f / Z;
    const float depth = S1 * invZ;

    float d0f = dv0 - depth;
    float d1f = dv1 - depth;
    float Svar = fmaf(e0, d0f * d0f, e1 * (d1f * d1f));
#pragma unroll
    for (int off = 16; off > 0; off >>= 1)
        Svar += __shfl_xor_sync(0xffffffffu, Svar, off);

    if (lane == 0) {
        const float var = Svar * invZ;
        const float hc = sqrtf(fmaxf(var, 1e-12f));
        out[pix] = depth;
        out[NPIX + pix] = fmaxf(depth - hc, nearv);
        out[2 * NPIX + pix] = fminf(depth + hc, farv);
    }
}

// ---------------------------------------------------------------------------
extern "C" void kernel_launch(void* const* d_in, const int* in_sizes, int n_in,
                              void* d_out, int out_size)
{
    const float* src_feat = (const float*)d_in[0];
    const float* src_exts = (const float*)d_in[1];
    const float* src_ints = (const float*)d_in[2];
    const float* tar_exts = (const float*)d_in[3];
    const float* tar_ints = (const float*)d_in[4];
    const float* near_far = (const float*)d_in[5];
    (void)in_sizes; (void)n_in; (void)out_size;

    setup_kernel<<<1, 32>>>(src_exts, src_ints, tar_exts, tar_ints);

    pair_build_kernel<<<(2 * NV * HS * XP + 255) / 256, 256>>>(src_feat);

    dim3 cg(NPIX / 32, ND / 8);
    cost_kernel<<<cg, 256>>>(near_far);

    depth_kernel<<<NPIX / 8, 256>>>(near_far, (float*)d_out);
}

// round 15
// speedup vs baseline: 1.4790x; 1.0522x over previous
#include <cuda_runtime.h>
#include <cuda_fp16.h>
#include <math.h>

#define HT 128
#define WT 128
#define HS 256
#define WS 256
#define NC 32
#define NV 3
#define ND 48
#define NPIX (HT * WT)
#define XP 128                      // x-pair count per row
#define PAIR_BYTES 128              // one pair-line: 32 ch x (L,R) half

__device__ __forceinline__ __half2 u32_as_h2(unsigned int u) {
    return *reinterpret_cast<__half2*>(&u);
}
__device__ __forceinline__ unsigned int h2_as_u32(__half2 h) {
    return *reinterpret_cast<unsigned int*>(&h);
}

// Static scratch (no allocs allowed)
// pair layout: [parity][v][y][xp] -> 128B line: half2(L_c, R_c) for c=0..31
__device__ __half d_pairH[2 * NV * HS * XP * 2 * NC];   // 25.2MB
__device__ float  d_costT[NPIX * ND];                   // cost volume (pix, d)
__device__ float  d_proj[NV * 12];

// ---------------------------------------------------------------------------
// Kernel 1: projection matrices via structured inverse
// ---------------------------------------------------------------------------
__global__ void setup_kernel(const float* __restrict__ src_exts,
                             const float* __restrict__ src_ints,
                             const float* __restrict__ tar_exts,
                             const float* __restrict__ tar_ints)
{
    if (threadIdx.x != 0) return;
    double B[3][3], tv[3];
    for (int i = 0; i < 3; i++) {
        for (int j = 0; j < 3; j++) {
            double s = 0.0;
            for (int k = 0; k < 3; k++)
                s += (double)tar_ints[i * 3 + k] * (double)tar_exts[k * 4 + j];
            B[i][j] = s;
        }
        double s = 0.0;
        for (int k = 0; k < 3; k++)
            s += (double)tar_ints[i * 3 + k] * (double)tar_exts[k * 4 + 3];
        tv[i] = s;
    }
    double c00 = B[1][1] * B[2][2] - B[1][2] * B[2][1];
    double c01 = B[1][2] * B[2][0] - B[1][0] * B[2][2];
    double c02 = B[1][0] * B[2][1] - B[1][1] * B[2][0];
    double det = B[0][0] * c00 + B[0][1] * c01 + B[0][2] * c02;
    double id = 1.0 / det;
    double Binv[3][3];
    Binv[0][0] = c00 * id;
    Binv[1][0] = c01 * id;
    Binv[2][0] = c02 * id;
    Binv[0][1] = (B[0][2] * B[2][1] - B[0][1] * B[2][2]) * id;
    Binv[1][1] = (B[0][0] * B[2][2] - B[0][2] * B[2][0]) * id;
    Binv[2][1] = (B[0][1] * B[2][0] - B[0][0] * B[2][1]) * id;
    Binv[0][2] = (B[0][1] * B[1][2] - B[0][2] * B[1][1]) * id;
    Binv[1][2] = (B[0][2] * B[1][0] - B[0][0] * B[1][2]) * id;
    Binv[2][2] = (B[0][0] * B[1][1] - B[0][1] * B[1][0]) * id;
    double mt[3];
    for (int i = 0; i < 3; i++)
        mt[i] = -(Binv[i][0] * tv[0] + Binv[i][1] * tv[1] + Binv[i][2] * tv[2]);

    for (int v = 0; v < NV; v++) {
        const float* K = src_ints + v * 9;
        const float* E = src_exts + v * 16;
        double A[3][4];
        for (int i = 0; i < 3; i++)
            for (int j = 0; j < 4; j++) {
                double s = 0.0;
                for (int k = 0; k < 3; k++)
                    s += (double)K[i * 3 + k] * (double)E[k * 4 + j];
                A[i][j] = s;
            }
        for (int i = 0; i < 3; i++) {
            for (int j = 0; j < 3; j++) {
                double s = A[i][0] * Binv[0][j] + A[i][1] * Binv[1][j] + A[i][2] * Binv[2][j];
                d_proj[v * 12 + i * 4 + j] = (float)s;
            }
            double s = A[i][0] * mt[0] + A[i][1] * mt[1] + A[i][2] * mt[2] + A[i][3];
            d_proj[v * 12 + i * 4 + 3] = (float)s;
        }
    }
}

// ---------------------------------------------------------------------------
// Kernel 2: build fp16 interleaved pair lines from (V,C,H,W) fp32 src
// ---------------------------------------------------------------------------
__global__ void pair_build_kernel(const float* __restrict__ src)
{
    int idx = blockIdx.x * blockDim.x + threadIdx.x;     // 2*NV*HS*XP
    if (idx >= 2 * NV * HS * XP) return;
    int xp = idx & (XP - 1);
    int y  = (idx >> 7) & (HS - 1);
    int pv = idx >> 15;            // parity*NV + v
    int v  = pv % NV;
    int parity = pv / NV;
    int xL = 2 * xp + parity;
    int dR = (xL + 1 < WS) ? 1 : 0;

    const float* base = src + ((size_t)(v * NC) * HS + y) * WS + xL;
    __half2 buf[NC];
#pragma unroll
    for (int c = 0; c < NC; c++) {
        float L = base[(size_t)c * HS * WS];
        float R = base[(size_t)c * HS * WS + dR];
        buf[c] = __floats2half2_rn(L, R);
    }
    uint4* out = reinterpret_cast<uint4*>((char*)d_pairH + (size_t)idx * PAIR_BYTES);
    const uint4* bp = reinterpret_cast<const uint4*>(buf);
#pragma unroll
    for (int q = 0; q < 8; q++) out[q] = bp[q];
}

// ---------------------------------------------------------------------------
// Kernel 3: cost volume. Block = 32 px x 8 depths. Staging packs ALL per-
// (px,d,v) metadata into ONE uint4 {W01_h2, W23_h2, off_y0, off_y1}.
// Main loop: 1 LDS.128 + 2 LDG.128 per px-view; fp16 HMUL2/HFMA2 blend.
// ---------------------------------------------------------------------------
__global__ void __launch_bounds__(256, 4)
cost_kernel(const float* __restrict__ nearfar)
{
    __shared__ uint4 s_meta[8][NV][32];   // {h2(w00,w01), h2(w10,w11), oy0, oy1}
    __shared__ float s_res[32][8];

    const int tid  = threadIdx.x;
    const int pix0 = blockIdx.x * 32;
    const int d0   = blockIdx.y * 8;

    // ---- staging: 768 coord tasks, 3 per thread ----
#pragma unroll
    for (int e = tid; e < 8 * NV * 32; e += 256) {
        const int p  = e & 31;
        const int v  = (e >> 5) % NV;
        const int dd = e / (NV * 32);
        const int pix = pix0 + p;
        const int d   = d0 + dd;

        const float nearv = nearfar[pix];
        const float farv  = nearfar[NPIX + pix];
        const float depth = fmaf((farv - nearv) * (1.0f / (ND - 1)), (float)d, nearv);
        const int x = pix & (WT - 1);
        const int y = pix >> 7;
        const float X = (float)x + 0.5f;
        const float Y = (float)y + 0.5f;

        const float* P = d_proj + v * 12;
        float px_ = fmaf(fmaf(P[0], X, fmaf(P[1], Y, P[2])), depth, P[3]);
        float py_ = fmaf(fmaf(P[4], X, fmaf(P[5], Y, P[6])), depth, P[7]);
        float pz_ = fmaf(fmaf(P[8], X, fmaf(P[9], Y, P[10])), depth, P[11]);
        pz_ = fmaxf(pz_, 1e-6f);
        float gx = px_ / pz_ - 0.5f;
        float gy = py_ / pz_ - 0.5f;
        gx = fminf(fmaxf(gx, -1.0e6f), 1.0e6f);
        gy = fminf(fmaxf(gy, -1.0e6f), 1.0e6f);
        float x0f = floorf(gx), y0f = floorf(gy);
        float wx = gx - x0f, wy = gy - y0f;
        int x0 = (int)x0f, y0 = (int)y0f;
        int x1 = x0 + 1, y1 = y0 + 1;
        float w00 = (1.f - wy) * (1.f - wx);
        float w01 = (1.f - wy) * wx;
        float w10 = wy * (1.f - wx);
        float w11 = wy * wx;
        bool vx0 = ((unsigned)x0 < WS);
        bool vx1 = ((unsigned)x1 < WS);
        bool vy0 = ((unsigned)y0 < HS);
        bool vy1 = ((unsigned)y1 < HS);
        if (!(vy0 & vx0)) w00 = 0.f;
        if (!(vy0 & vx1)) w01 = 0.f;
        if (!(vy1 & vx0)) w10 = 0.f;
        if (!(vy1 & vx1)) w11 = 0.f;
        int cx0 = min(max(x0, 0), WS - 1);
        int cy0 = min(max(y0, 0), HS - 1);
        int cx1 = min(max(x1, 0), WS - 1);
        int cy1 = min(max(y1, 0), HS - 1);

        // x-fold: both x taps clamp to same column -> all weight to L element
        if (cx1 == cx0) {
            w00 += w01; w01 = 0.f;
            w10 += w11; w11 = 0.f;
        }
        const int parity = cx0 & 1;
        const int xp = cx0 >> 1;
        const int pvb = (parity * NV + v) * HS;

        uint4 M;
        M.x = h2_as_u32(__floats2half2_rn(w00, w01));
        M.y = h2_as_u32(__floats2half2_rn(w10, w11));
        M.z = (unsigned)(((pvb + cy0) * XP + xp) * PAIR_BYTES);
        M.w = (unsigned)(((pvb + cy1) * XP + xp) * PAIR_BYTES);
        s_meta[dd][v][p] = M;
    }
    __syncthreads();

    // ---- main loop: warp = 4 px x 8 channel groups (4 channels each) ----
    const int lane = tid & 31;
    const int w    = tid >> 5;
    const int cg   = lane & 7;
    const int pxl  = lane >> 3;
    const int pl   = w * 4 + pxl;

    const char* fbase = (const char*)d_pairH + cg * 16;

#pragma unroll
    for (int dd = 0; dd < 8; dd++) {
        float s1[4] = {0.f, 0.f, 0.f, 0.f};
        float S2 = 0.f;
#pragma unroll
        for (int v = 0; v < NV; v++) {
            const uint4 M = s_meta[dd][v][pl];
            const __half2 W01 = u32_as_h2(M.x);
            const __half2 W23 = u32_as_h2(M.y);

            const uint4 r0 = *reinterpret_cast<const uint4*>(fbase + M.z);
            const uint4 r1 = *reinterpret_cast<const uint4*>(fbase + M.w);

#pragma unroll
            for (int j = 0; j < 4; j++) {
                __half2 t = __hmul2(W01, u32_as_h2((&r0.x)[j]));
                t = __hfma2(W23, u32_as_h2((&r1.x)[j]), t);
                const float2 f = __half22float2(t);
                const float wv = f.x + f.y;
                s1[j] += wv;
                S2 = fmaf(wv, wv, S2);
            }
        }

        float q = fmaf(s1[0], s1[0], fmaf(s1[1], s1[1],
                  fmaf(s1[2], s1[2], s1[3] * s1[3])));
        float r = fmaf((float)NV, S2, -q);
#pragma unroll
        for (int off = 1; off < 8; off <<= 1)
            r += __shfl_xor_sync(0xffffffffu, r, off);
        if (cg == 0)
            s_res[pl][dd] = r * (1.0f / (NV * NV * NC));
    }
    __syncthreads();

    // ---- coalesced transposed write: (pix, d) ----
    {
        const int pl2 = tid >> 3;
        const int dd2 = tid & 7;
        d_costT[(pix0 + pl2) * ND + d0 + dd2] = s_res[pl2][dd2];
    }
}

// ---------------------------------------------------------------------------
// Kernel 4: warp-per-pixel softmax over depth -> expected depth, CI
// ---------------------------------------------------------------------------
__global__ void __launch_bounds__(256)
depth_kernel(const float* __restrict__ nearfar, float* __restrict__ out)
{
    const int lane = threadIdx.x & 31;
    const int wid  = threadIdx.x >> 5;
    const int pix  = blockIdx.x * 8 + wid;

    const float nearv = nearfar[pix];
    const float farv  = nearfar[NPIX + pix];
    const float step  = (farv - nearv) * (1.0f / (ND - 1));
    const float* cp = d_costT + pix * ND;

    const float n0 = -cp[lane];
    const float n1 = (lane < 16) ? -cp[32 + lane] : -1e30f;

    float m = fmaxf(n0, n1);
#pragma unroll
    for (int off = 16; off > 0; off >>= 1)
        m = fmaxf(m, __shfl_xor_sync(0xffffffffu, m, off));

    const float dv0 = fmaf(step, (float)lane, nearv);
    const float dv1 = fmaf(step, (float)(32 + lane), nearv);
    const float e0 = __expf(n0 - m);
    const float e1 = (lane < 16) ? __expf(n1 - m) : 0.f;

    float Z  = e0 + e1;
    float S1 = fmaf(e0, dv0, e1 * dv1);
#pragma unroll
    for (int off = 16; off > 0; off >>= 1) {
        Z  += __shfl_xor_sync(0xffffffffu, Z, off);
        S1 += __shfl_xor_sync(0xffffffffu, S1, off);
    }
    const float invZ = 1.0f / Z;
    const float depth = S1 * invZ;

    float d0f = dv0 - depth;
    float d1f = dv1 - depth;
    float Svar = fmaf(e0, d0f * d0f, e1 * (d1f * d1f));
#pragma unroll
    for (int off = 16; off > 0; off >>= 1)
        Svar += __shfl_xor_sync(0xffffffffu, Svar, off);

    if (lane == 0) {
        const float var = Svar * invZ;
        const float hc = sqrtf(fmaxf(var, 1e-12f));
        out[pix] = depth;
        out[NPIX + pix] = fmaxf(depth - hc, nearv);
        out[2 * NPIX + pix] = fminf(depth + hc, farv);
    }
}

// ---------------------------------------------------------------------------
extern "C" void kernel_launch(void* const* d_in, const int* in_sizes, int n_in,
                              void* d_out, int out_size)
{
    const float* src_feat = (const float*)d_in[0];
    const float* src_exts = (const float*)d_in[1];
    const float* src_ints = (const float*)d_in[2];
    const float* tar_exts = (const float*)d_in[3];
    const float* tar_ints = (const float*)d_in[4];
    const float* near_far = (const float*)d_in[5];
    (void)in_sizes; (void)n_in; (void)out_size;

    setup_kernel<<<1, 32>>>(src_exts, src_ints, tar_exts, tar_ints);

    pair_build_kernel<<<(2 * NV * HS * XP + 255) / 256, 256>>>(src_feat);

    dim3 cg(NPIX / 32, ND / 8);
    cost_kernel<<<cg, 256>>>(near_far);

    depth_kernel<<<NPIX / 8, 256>>>(near_far, (float*)d_out);
}